// round 5
// baseline (speedup 1.0000x reference)
#include <cuda_runtime.h>
#include <math.h>

#define Bc 16
#define Sc 2048
#define Hc 1024
#define Nc 128
#define ROWS (Bc*Nc)          // 2048
#define MT 128                // GEMM M tile
#define NT 64                 // GEMM N tile
#define KC 16                 // GEMM K chunk
#define MTILES 17             // ceil(n0/128)+ceil(n1/128) <= 17 always
#define NTILES (Hc/NT)        // 16
#define KSEGS 5
#define KTOT (KSEGS*Hc)       // 5120

// ---------------- scratch (device globals; no runtime allocation) ----------
__device__ float g_Init[(size_t)ROWS*Hc];          // gathered rows   8.4 MB
__device__ float g_alpha[ROWS];
__device__ float g_X[(size_t)ROWS*4*Hc];           // x0..x3 per row 33.6 MB
__device__ int   g_perm[MTILES*MT];                // tile-padded row permutation
__device__ int   g_meta[4];                        // [0] = #tiles in group a=0

// ---------------- kernel 1: gather Init rows + alpha = sigmoid(Init@w_a) ---
__global__ void k_gather(const float* __restrict__ we, const int* __restrict__ ids,
                         const float* __restrict__ w_alpha, const float* __restrict__ b_alpha) {
    int row = blockIdx.x;
    int b = row >> 7;
    int id = ids[row];
    int idc = min(max(id, 0), Sc - 1);
    const float* src = we + ((size_t)b*Sc + idc)*Hc;
    float partial = 0.f;
    for (int h = threadIdx.x; h < Hc; h += 256) {
        float v = src[h];
        g_Init[(size_t)row*Hc + h] = v;
        partial += v * w_alpha[h];
    }
    __shared__ float red[256];
    red[threadIdx.x] = partial;
    __syncthreads();
    for (int s = 128; s > 0; s >>= 1) {
        if (threadIdx.x < s) red[threadIdx.x] += red[threadIdx.x + s];
        __syncthreads();
    }
    if (threadIdx.x == 0) {
        float x = red[0] + b_alpha[0];
        g_alpha[row] = 1.f / (1.f + expf(-x));
    }
}

// ---------------- kernel 2: sorted-prefix aggregation -> x0..x3 ------------
// x0 = prefix(c=0, num_j<num_i), x1 = prefix(c=1),
// x2 = A0 - x0 - self(c==0),     x3 = A1 - x1 - self(c==1)
// all scaled by mask_i/denom (wgt/denom folded in).
__global__ void k_agg(const float* __restrict__ numbers, const int* __restrict__ is_resp,
                      const int* __restrict__ ids) {
    int b = blockIdx.x;
    int h = blockIdx.y * 256 + threadIdx.x;
    int tid = threadIdx.x;
    __shared__ float s_num[Nc], s_w[Nc], s_scale[Nc];
    __shared__ int s_order[Nc], s_c[Nc];
    __shared__ unsigned char s_newgrp[Nc];
    __shared__ int s_cnt;
    if (tid == 0) s_cnt = 0;
    __syncthreads();
    if (tid < Nc) {
        int i = tid;
        s_num[i] = numbers[b*Nc + i];
        s_c[i] = (is_resp[b*Nc + i] == 1) ? 1 : 0;
        int valid = (ids[b*Nc + i] >= 0) ? 1 : 0;
        s_w[i] = valid ? g_alpha[b*Nc + i] : 0.f;
        s_scale[i] = (float)valid;
        if (valid) atomicAdd(&s_cnt, 1);
    }
    __syncthreads();
    float denom = fmaxf((float)(s_cnt - 1), 1.f);
    if (tid < Nc) {
        int i = tid;
        float ni = s_num[i];
        int pos = 0;
        for (int j = 0; j < Nc; j++) {
            float nj = s_num[j];
            pos += (int)((nj < ni) || (nj == ni && j < i));   // strict total order
        }
        s_order[pos] = i;
        s_scale[i] = s_scale[i] / denom;
    }
    __syncthreads();
    if (tid < Nc) {
        int t = tid;
        s_newgrp[t] = (t == 0) || (s_num[s_order[t]] != s_num[s_order[t-1]]);
    }
    __syncthreads();

    const float* initb = g_Init + (size_t)b*Nc*Hc;
    float A0 = 0.f, A1 = 0.f;
    for (int j = 0; j < Nc; j++) {
        float wv = s_w[j] * initb[(size_t)j*Hc + h];
        if (s_c[j]) A1 += wv; else A0 += wv;
    }
    float p0 = 0.f, p1 = 0.f, r0 = 0.f, r1 = 0.f;
    for (int t = 0; t < Nc; t++) {
        int j = s_order[t];
        if (s_newgrp[t]) { p0 = r0; p1 = r1; }    // strict-prefix snapshot (tie-safe)
        float v = initb[(size_t)j*Hc + h];
        float wv = s_w[j] * v;
        float sc = s_scale[j];
        float sub0 = A0 - p0 - (s_c[j] == 0 ? wv : 0.f);
        float sub1 = A1 - p1 - (s_c[j] == 1 ? wv : 0.f);
        size_t xb = ((size_t)(b*Nc + j))*(4*Hc) + h;
        g_X[xb         ] = p0 * sc;
        g_X[xb +   Hc  ] = p1 * sc;
        g_X[xb + 2*Hc  ] = sub0 * sc;
        g_X[xb + 3*Hc  ] = sub1 * sc;
        if (s_c[j]) r1 += wv; else r0 += wv;
    }
}

// ---------------- kernel 3: row permutation grouped by resp, tile-padded ---
__global__ void k_perm(const int* __restrict__ is_resp) {
    __shared__ int red[256];
    __shared__ int cnt[2];
    int tid = threadIdx.x;
    int local0 = 0;
    for (int r = tid; r < ROWS; r += 256)
        local0 += (is_resp[r] == 1) ? 0 : 1;
    red[tid] = local0;
    __syncthreads();
    for (int s = 128; s > 0; s >>= 1) {
        if (tid < s) red[tid] += red[tid + s];
        __syncthreads();
    }
    int n0 = red[0];
    int g0t = (n0 + MT - 1) / MT;
    if (tid == 0) { cnt[0] = 0; cnt[1] = g0t * MT; g_meta[0] = g0t; }
    for (int s = tid; s < MTILES*MT; s += 256) g_perm[s] = -1;
    __syncthreads();
    for (int r = tid; r < ROWS; r += 256) {
        int grp = (is_resp[r] == 1) ? 1 : 0;
        int pos = atomicAdd(&cnt[grp], 1);
        g_perm[pos] = r;
    }
}

// ---------------- kernel 4: gathered GEMM  [2048 x 5120] @ [5120 x 1024] ---
// seg0: Init @ w_f (w_f stored [h,k]); seg1..4: x0..x3 @ W_r^T (W_r stored [k,h]).
// Weight set per M-tile depends on resp-group a.
__global__ void __launch_bounds__(256, 2) k_gemm(const float* __restrict__ w_f,
                                                 const float* __restrict__ b_f,
                                                 const float* __restrict__ W_r,
                                                 float* __restrict__ out) {
    __shared__ float As[KC][MT];       // [k][m]
    __shared__ float Bs[KC][NT + 4];   // [k][n], padded stride 68
    __shared__ int s_rows[MT];
    int tid = threadIdx.x;
    int mt = blockIdx.y, nt = blockIdx.x;
    int ncol = nt * NT;
    int g0t = g_meta[0];
    int a = (mt >= g0t) ? 1 : 0;
    if (tid < MT) s_rows[tid] = g_perm[mt*MT + tid];
    __syncthreads();

    int mA = tid & 127;
    int kA = (tid >> 7) * 8;           // 0 or 8
    int rowA = s_rows[mA];
    size_t rsafe = (rowA >= 0) ? (size_t)rowA : 0;
    const float* aInit = g_Init + rsafe*Hc;
    const float* aX    = g_X    + rsafe*4*Hc;
    const float* Bptr[5] = {
        w_f,
        W_r + (size_t)(4 + 2*a)*Hc*Hc,
        W_r + (size_t)(5 + 2*a)*Hc*Hc,
        W_r + (size_t)(2*a    )*Hc*Hc,
        W_r + (size_t)(2*a + 1)*Hc*Hc
    };
    int m0 = (tid >> 4) * 8;
    int n0 = (tid & 15) * 4;

    float acc[8][4];
    #pragma unroll
    for (int i = 0; i < 8; i++)
        #pragma unroll
        for (int j = 0; j < 4; j++) acc[i][j] = 0.f;

    for (int kc = 0; kc < KTOT/KC; kc++) {
        int seg = kc >> 6;             // 64 KC-chunks per 1024-wide segment
        int kin = (kc & 63) * KC;

        // stage A fragment (8 floats along k for row mA)
        float4 av0, av1;
        if (rowA >= 0) {
            const float* base = (seg == 0) ? (aInit + kin + kA)
                                           : (aX + (size_t)(seg - 1)*Hc + kin + kA);
            av0 = *(const float4*)(base);
            av1 = *(const float4*)(base + 4);
        } else {
            av0 = make_float4(0.f, 0.f, 0.f, 0.f);
            av1 = av0;
        }

        // stage B fragment (4 floats)
        float bv[4]; int bk[4], bn[4];
        if (seg == 0) {
            int n  = tid & 63;
            int kh = tid >> 6;         // 0..3
            #pragma unroll
            for (int q = 0; q < 4; q++) {
                int k = kh + q*4;
                bk[q] = k; bn[q] = n;
                bv[q] = w_f[(size_t)(kin + k)*Hc + ncol + n];
            }
        } else {
            int hh = tid & 15;
            int n  = tid >> 4;         // 0..15
            const float* Bp = Bptr[seg];
            #pragma unroll
            for (int q = 0; q < 4; q++) {
                int nn = n + q*16;
                bk[q] = hh; bn[q] = nn;
                bv[q] = Bp[(size_t)(ncol + nn)*Hc + kin + hh];
            }
        }

        __syncthreads();
        As[kA + 0][mA] = av0.x; As[kA + 1][mA] = av0.y;
        As[kA + 2][mA] = av0.z; As[kA + 3][mA] = av0.w;
        As[kA + 4][mA] = av1.x; As[kA + 5][mA] = av1.y;
        As[kA + 6][mA] = av1.z; As[kA + 7][mA] = av1.w;
        #pragma unroll
        for (int q = 0; q < 4; q++) Bs[bk[q]][bn[q]] = bv[q];
        __syncthreads();

        #pragma unroll
        for (int k = 0; k < KC; k++) {
            float4 a0 = *(const float4*)&As[k][m0];
            float4 a1 = *(const float4*)&As[k][m0 + 4];
            float4 b4 = *(const float4*)&Bs[k][n0];
            float ar[8] = {a0.x, a0.y, a0.z, a0.w, a1.x, a1.y, a1.z, a1.w};
            float br[4] = {b4.x, b4.y, b4.z, b4.w};
            #pragma unroll
            for (int i = 0; i < 8; i++)
                #pragma unroll
                for (int j = 0; j < 4; j++)
                    acc[i][j] += ar[i] * br[j];
        }
    }

    // epilogue: + b_f, relu, scatter to real row
    #pragma unroll
    for (int i = 0; i < 8; i++) {
        int row = s_rows[m0 + i];
        if (row < 0) continue;
        float* orow = out + (size_t)row*Hc + ncol + n0;
        #pragma unroll
        for (int j = 0; j < 4; j++) {
            float v = acc[i][j] + b_f[ncol + n0 + j];
            orow[j] = v > 0.f ? v : 0.f;
        }
    }
}

// ---------------------------------------------------------------------------
extern "C" void kernel_launch(void* const* d_in, const int* in_sizes, int n_in,
                              void* d_out, int out_size) {
    const float* word_emb = (const float*)d_in[0];
    const int*   num_ids  = (const int*)  d_in[1];
    const int*   is_resp  = (const int*)  d_in[2];
    const float* numbers  = (const float*)d_in[3];
    const float* w_alpha  = (const float*)d_in[4];
    const float* b_alpha  = (const float*)d_in[5];
    const float* w_f      = (const float*)d_in[6];
    const float* b_f      = (const float*)d_in[7];
    const float* W_r      = (const float*)d_in[8];
    float* out = (float*)d_out;

    k_gather<<<ROWS, 256>>>(word_emb, num_ids, w_alpha, b_alpha);
    k_agg<<<dim3(Bc, Hc/256), 256>>>(numbers, is_resp, num_ids);
    k_perm<<<1, 256>>>(is_resp);
    k_gemm<<<dim3(NTILES, MTILES), 256>>>(w_f, b_f, W_r, out);
}

// round 9
// speedup vs baseline: 1.8421x; 1.8421x over previous
#include <cuda_runtime.h>
#include <math.h>
#include <stdint.h>

#define Bc 16
#define Sc 2048
#define Hc 1024
#define Nc 128
#define ROWS (Bc*Nc)          // 2048
#define KSEGS 5
#define KTOT (KSEGS*Hc)       // 5120
#define MT 128                // M tile
#define NTt 128               // N tile
#define KC 32                 // K chunk (fp32)
#define NCH (KTOT/KC)         // 160
#define MTILES 17
#define NTILES (Hc/NTt)       // 8

// smem strides (in elements)
#define ASTR 68               // float2 per k-row of A (64 + 4 pad)
#define BSTR 136              // float  per k-row of B (128 + 8 pad)
#define ABUF (KC*ASTR)        // 2176 float2 per buffer
#define BBUF (KC*BSTR)        // 4352 float  per buffer

// ---------------- scratch (device globals) ---------------------------------
__device__ float g_A[(size_t)ROWS*KTOT];     // [Init|x0..x3] rows, tf32-rounded
__device__ float g_alpha[ROWS];
__device__ float g_wfT[(size_t)Hc*Hc];       // w_f transposed, K-major, tf32-rounded
__device__ float g_Wr[(size_t)8*Hc*Hc];      // W_r tf32-rounded
__device__ int   g_perm[MTILES*MT];
__device__ int   g_meta[4];

// ---------------- helpers ---------------------------------------------------
__device__ __forceinline__ float to_tf32(float x){
    float r; asm("cvt.rna.tf32.f32 %0, %1;" : "=f"(r) : "f"(x)); return r;
}
__device__ __forceinline__ void mma8(float* c, const uint32_t* a, const uint32_t* b){
    asm volatile("mma.sync.aligned.m16n8k8.row.col.f32.tf32.tf32.f32 "
        "{%0,%1,%2,%3}, {%4,%5,%6,%7}, {%8,%9}, {%0,%1,%2,%3};"
        : "+f"(c[0]), "+f"(c[1]), "+f"(c[2]), "+f"(c[3])
        : "r"(a[0]), "r"(a[1]), "r"(a[2]), "r"(a[3]), "r"(b[0]), "r"(b[1]));
}

// ---------------- kernel 1: gather Init rows + alpha -----------------------
__global__ void k_gather(const float* __restrict__ we, const int* __restrict__ ids,
                         const float* __restrict__ w_alpha, const float* __restrict__ b_alpha) {
    int row = blockIdx.x;
    int b = row >> 7;
    int id = ids[row];
    int idc = min(max(id, 0), Sc - 1);
    const float* src = we + ((size_t)b*Sc + idc)*Hc;
    float partial = 0.f;
    #pragma unroll 4
    for (int h = threadIdx.x; h < Hc; h += 256) {
        float v = src[h];
        g_A[(size_t)row*KTOT + h] = to_tf32(v);
        partial += v * w_alpha[h];
    }
    __shared__ float red[256];
    red[threadIdx.x] = partial;
    __syncthreads();
    for (int s = 128; s > 0; s >>= 1) {
        if (threadIdx.x < s) red[threadIdx.x] += red[threadIdx.x + s];
        __syncthreads();
    }
    if (threadIdx.x == 0) {
        float x = red[0] + b_alpha[0];
        g_alpha[row] = 1.f / (1.f + expf(-x));
    }
}

// ---------------- kernel 1b: transpose w_f -> K-major (tf32) ---------------
__global__ void k_transpose(const float* __restrict__ w) {
    __shared__ float t[32][33];
    int bx = blockIdx.x*32, by = blockIdx.y*32;
    for (int r = threadIdx.y; r < 32; r += 8)
        t[r][threadIdx.x] = w[(size_t)(by + r)*Hc + bx + threadIdx.x];
    __syncthreads();
    for (int r = threadIdx.y; r < 32; r += 8)
        g_wfT[(size_t)(bx + r)*Hc + by + threadIdx.x] = to_tf32(t[threadIdx.x][r]);
}

// ---------------- kernel 1c: round W_r to tf32 -----------------------------
__global__ void k_round(const float* __restrict__ w) {
    size_t i = ((size_t)blockIdx.x*256 + threadIdx.x)*4;
    float4 v = *(const float4*)(w + i);
    v.x = to_tf32(v.x); v.y = to_tf32(v.y); v.z = to_tf32(v.z); v.w = to_tf32(v.w);
    *(float4*)(g_Wr + i) = v;
}

// ---------------- kernel 2: sorted-prefix aggregation -> segs 1..4 ---------
__global__ void k_agg(const float* __restrict__ numbers, const int* __restrict__ is_resp,
                      const int* __restrict__ ids) {
    int b = blockIdx.x;
    int h = blockIdx.y * 256 + threadIdx.x;
    int tid = threadIdx.x;
    __shared__ float s_num[Nc], s_w[Nc], s_scale[Nc];
    __shared__ int s_order[Nc], s_c[Nc];
    __shared__ unsigned char s_newgrp[Nc];
    __shared__ int s_cnt;
    if (tid == 0) s_cnt = 0;
    __syncthreads();
    if (tid < Nc) {
        int i = tid;
        s_num[i] = numbers[b*Nc + i];
        s_c[i] = (is_resp[b*Nc + i] == 1) ? 1 : 0;
        int valid = (ids[b*Nc + i] >= 0) ? 1 : 0;
        s_w[i] = valid ? g_alpha[b*Nc + i] : 0.f;
        s_scale[i] = (float)valid;
        if (valid) atomicAdd(&s_cnt, 1);
    }
    __syncthreads();
    float denom = fmaxf((float)(s_cnt - 1), 1.f);
    if (tid < Nc) {
        int i = tid;
        float ni = s_num[i];
        int pos = 0;
        for (int j = 0; j < Nc; j++) {
            float nj = s_num[j];
            pos += (int)((nj < ni) || (nj == ni && j < i));
        }
        s_order[pos] = i;
        s_scale[i] = s_scale[i] / denom;
    }
    __syncthreads();
    if (tid < Nc) {
        int t = tid;
        s_newgrp[t] = (t == 0) || (s_num[s_order[t]] != s_num[s_order[t-1]]);
    }
    __syncthreads();

    const float* initb = g_A + (size_t)(b*Nc)*KTOT;
    float A0 = 0.f, A1 = 0.f;
    #pragma unroll 4
    for (int j = 0; j < Nc; j++) {
        float wv = s_w[j] * initb[(size_t)j*KTOT + h];
        if (s_c[j]) A1 += wv; else A0 += wv;
    }
    float p0 = 0.f, p1 = 0.f, r0 = 0.f, r1 = 0.f;
    for (int t = 0; t < Nc; t++) {
        int j = s_order[t];
        if (s_newgrp[t]) { p0 = r0; p1 = r1; }
        float v = initb[(size_t)j*KTOT + h];
        float wv = s_w[j] * v;
        float sc = s_scale[j];
        float sub0 = A0 - p0 - (s_c[j] == 0 ? wv : 0.f);
        float sub1 = A1 - p1 - (s_c[j] == 1 ? wv : 0.f);
        size_t xb = (size_t)(b*Nc + j)*KTOT + Hc + h;
        g_A[xb        ] = to_tf32(p0 * sc);
        g_A[xb +   Hc ] = to_tf32(p1 * sc);
        g_A[xb + 2*Hc ] = to_tf32(sub0 * sc);
        g_A[xb + 3*Hc ] = to_tf32(sub1 * sc);
        if (s_c[j]) r1 += wv; else r0 += wv;
    }
}

// ---------------- kernel 3: row permutation grouped by resp ----------------
__global__ void k_perm(const int* __restrict__ is_resp) {
    __shared__ int red[256];
    __shared__ int cnt[2];
    int tid = threadIdx.x;
    int local0 = 0;
    for (int r = tid; r < ROWS; r += 256)
        local0 += (is_resp[r] == 1) ? 0 : 1;
    red[tid] = local0;
    __syncthreads();
    for (int s = 128; s > 0; s >>= 1) {
        if (tid < s) red[tid] += red[tid + s];
        __syncthreads();
    }
    int n0 = red[0];
    int g0t = (n0 + MT - 1) / MT;
    if (tid == 0) { cnt[0] = 0; cnt[1] = g0t * MT; g_meta[0] = g0t; }
    for (int s = tid; s < MTILES*MT; s += 256) g_perm[s] = -1;
    __syncthreads();
    for (int r = tid; r < ROWS; r += 256) {
        int grp = (is_resp[r] == 1) ? 1 : 0;
        int pos = atomicAdd(&cnt[grp], 1);
        g_perm[pos] = r;
    }
}

// ---------------- kernel 4: tf32 mma.sync GEMM -----------------------------
// C[128x128] = A[128 x 5120 gathered] * B[5120 x 128]; bias + relu + scatter.
// 8 warps, warp tile 64x32 (4x4 m16n8k8 frags). Conflict-free smem layouts.
__global__ void __launch_bounds__(256, 1)
k_mma(const float* __restrict__ b_f, float* __restrict__ out) {
    extern __shared__ float sdyn[];
    float2* Abase = (float2*)sdyn;            // 2 x ABUF float2  (34816 B)
    float*  Bbase = sdyn + 2*ABUF*2;          // 2 x BBUF float   (34816 B)

    __shared__ int s_rows[MT];
    __shared__ const float* s_Bp[KSEGS];

    int tid = threadIdx.x;
    int wid = tid >> 5;
    int lane = tid & 31;
    int g = lane >> 2, tig = lane & 3;
    int wr = wid >> 2;                // 0..1  (64-row strip)
    int wc = wid & 3;                 // 0..3  (32-col strip)
    int mt = blockIdx.y, nt = blockIdx.x;
    int ncol = nt * NTt;

    if (tid < MT) s_rows[tid] = g_perm[mt*MT + tid];
    if (tid == 0) {
        int a = (mt >= g_meta[0]) ? 1 : 0;
        s_Bp[0] = g_wfT;
        s_Bp[1] = g_Wr + (size_t)(4 + 2*a)*Hc*Hc;
        s_Bp[2] = g_Wr + (size_t)(5 + 2*a)*Hc*Hc;
        s_Bp[3] = g_Wr + (size_t)(2*a    )*Hc*Hc;
        s_Bp[4] = g_Wr + (size_t)(2*a + 1)*Hc*Hc;
    }
    __syncthreads();

    // ---- producer thread maps -------------------------------------------
    // A: 1 unit/thread: (mp 0..63, koct 0..3). rows m=(mp>>3)*16+(mp&7), m+8.
    int mpA = tid & 63;
    int koA = tid >> 6;               // 0..3 -> k0 = 8*koA
    int mA0 = (mpA >> 3)*16 + (mpA & 7);
    int rA0 = s_rows[mA0], rA1 = s_rows[mA0 + 8];
    const float* pA0 = (rA0 >= 0) ? (g_A + (size_t)rA0*KTOT + 8*koA) : (const float*)0;
    const float* pA1 = (rA1 >= 0) ? (g_A + (size_t)rA1*KTOT + 8*koA) : (const float*)0;
    // B: 2 units/thread: (n 0..127, koct 0..3)
    int nB[2], koB[2];
    #pragma unroll
    for (int t = 0; t < 2; t++) {
        int u = tid + t*256;
        nB[t] = u & 127;
        koB[t] = u >> 7;              // 0..3
    }

    float acc[4][4][4];
    #pragma unroll
    for (int i = 0; i < 4; i++)
        #pragma unroll
        for (int j = 0; j < 4; j++)
            #pragma unroll
            for (int q = 0; q < 4; q++) acc[i][j][q] = 0.f;

    float4 avA[4];     // (m,k0),(m,k0+4),(m+8,k0),(m+8,k0+4)
    float4 bvB[2][2];  // per unit: (k0),(k0+4)

    // ---- load chunk kc into registers -----------------------------------
    auto ldg_chunk = [&](int kc) {
        size_t kb = (size_t)kc*KC;
        if (pA0) { avA[0] = *(const float4*)(pA0 + kb); avA[1] = *(const float4*)(pA0 + kb + 4); }
        else     { avA[0] = make_float4(0,0,0,0); avA[1] = avA[0]; }
        if (pA1) { avA[2] = *(const float4*)(pA1 + kb); avA[3] = *(const float4*)(pA1 + kb + 4); }
        else     { avA[2] = make_float4(0,0,0,0); avA[3] = avA[2]; }
        const float* Bs = s_Bp[kc >> 5];
        int kin = (kc & 31) * KC;
        #pragma unroll
        for (int t = 0; t < 2; t++) {
            const float* p = Bs + (size_t)(ncol + nB[t])*Hc + kin + 8*koB[t];
            bvB[t][0] = *(const float4*)p;
            bvB[t][1] = *(const float4*)(p + 4);
        }
    };
    // ---- store staged registers into smem buffer b ----------------------
    auto sts_chunk = [&](int b) {
        float2* Ap = Abase + b*ABUF;
        float*  Bp = Bbase + b*BBUF;
        #pragma unroll
        for (int q = 0; q < 4; q++) {
            float a00 = (&avA[0].x)[q], a01 = (&avA[1].x)[q];
            float a10 = (&avA[2].x)[q], a11 = (&avA[3].x)[q];
            Ap[(8*koA + q    )*ASTR + mpA] = make_float2(a00, a10);
            Ap[(8*koA + q + 4)*ASTR + mpA] = make_float2(a01, a11);
        }
        #pragma unroll
        for (int t = 0; t < 2; t++)
            #pragma unroll
            for (int q = 0; q < 4; q++) {
                Bp[(8*koB[t] + q    )*BSTR + nB[t]] = (&bvB[t][0].x)[q];
                Bp[(8*koB[t] + q + 4)*BSTR + nB[t]] = (&bvB[t][1].x)[q];
            }
    };

    ldg_chunk(0);
    sts_chunk(0);
    __syncthreads();

    for (int kc = 0; kc < NCH; kc++) {
        int cur = kc & 1;
        if (kc + 1 < NCH) ldg_chunk(kc + 1);

        const float2* Ap = Abase + cur*ABUF;
        const float*  Bp = Bbase + cur*BBUF;
        #pragma unroll
        for (int ks = 0; ks < 4; ks++) {
            uint32_t afr[4][4], bfr[4][2];
            int kr0 = 8*ks + tig, kr1 = kr0 + 4;
            #pragma unroll
            for (int rm = 0; rm < 4; rm++) {
                int mp = (4*wr + rm)*8 + g;
                float2 x = Ap[kr0*ASTR + mp];
                float2 y = Ap[kr1*ASTR + mp];
                afr[rm][0] = __float_as_uint(x.x);
                afr[rm][1] = __float_as_uint(x.y);
                afr[rm][2] = __float_as_uint(y.x);
                afr[rm][3] = __float_as_uint(y.y);
            }
            #pragma unroll
            for (int nb = 0; nb < 4; nb++) {
                int n = 32*wc + 8*nb + g;
                bfr[nb][0] = __float_as_uint(Bp[kr0*BSTR + n]);
                bfr[nb][1] = __float_as_uint(Bp[kr1*BSTR + n]);
            }
            #pragma unroll
            for (int rm = 0; rm < 4; rm++)
                #pragma unroll
                for (int nb = 0; nb < 4; nb++)
                    mma8(acc[rm][nb], afr[rm], bfr[nb]);
        }

        if (kc + 1 < NCH) sts_chunk(cur ^ 1);
        __syncthreads();
    }

    // ---- epilogue: bias + relu + scatter --------------------------------
    #pragma unroll
    for (int rm = 0; rm < 4; rm++) {
        int m0 = 64*wr + 16*rm + g;
        int row0 = s_rows[m0], row1 = s_rows[m0 + 8];
        #pragma unroll
        for (int nb = 0; nb < 4; nb++) {
            int col = ncol + 32*wc + 8*nb + 2*tig;
            float b0v = b_f[col], b1v = b_f[col + 1];
            if (row0 >= 0) {
                float v0 = acc[rm][nb][0] + b0v; v0 = v0 > 0.f ? v0 : 0.f;
                float v1 = acc[rm][nb][1] + b1v; v1 = v1 > 0.f ? v1 : 0.f;
                *(float2*)(out + (size_t)row0*Hc + col) = make_float2(v0, v1);
            }
            if (row1 >= 0) {
                float v2 = acc[rm][nb][2] + b0v; v2 = v2 > 0.f ? v2 : 0.f;
                float v3 = acc[rm][nb][3] + b1v; v3 = v3 > 0.f ? v3 : 0.f;
                *(float2*)(out + (size_t)row1*Hc + col) = make_float2(v2, v3);
            }
        }
    }
}

// ---------------------------------------------------------------------------
extern "C" void kernel_launch(void* const* d_in, const int* in_sizes, int n_in,
                              void* d_out, int out_size) {
    const float* word_emb = (const float*)d_in[0];
    const int*   num_ids  = (const int*)  d_in[1];
    const int*   is_resp  = (const int*)  d_in[2];
    const float* numbers  = (const float*)d_in[3];
    const float* w_alpha  = (const float*)d_in[4];
    const float* b_alpha  = (const float*)d_in[5];
    const float* w_f      = (const float*)d_in[6];
    const float* b_f      = (const float*)d_in[7];
    const float* W_r      = (const float*)d_in[8];
    float* out = (float*)d_out;

    k_gather<<<ROWS, 256>>>(word_emb, num_ids, w_alpha, b_alpha);
    k_transpose<<<dim3(Hc/32, Hc/32), dim3(32, 8)>>>(w_f);
    k_round<<<(8*Hc*Hc)/(256*4), 256>>>(W_r);
    k_agg<<<dim3(Bc, Hc/256), 256>>>(numbers, is_resp, num_ids);
    k_perm<<<1, 256>>>(is_resp);

    cudaFuncSetAttribute(k_mma, cudaFuncAttributeMaxDynamicSharedMemorySize, 69632);
    k_mma<<<dim3(NTILES, MTILES), 256, 69632>>>(b_f, out);
}

// round 10
// speedup vs baseline: 1.9380x; 1.0521x over previous
#include <cuda_runtime.h>
#include <math.h>
#include <stdint.h>

#define Bc 16
#define Sc 2048
#define Hc 1024
#define Nc 128
#define ROWS (Bc*Nc)          // 2048
#define KSEGS 5
#define KTOT (KSEGS*Hc)       // 5120
#define MT 128                // M tile
#define NTt 128               // N tile
#define KC 32                 // K chunk (fp32)
#define NCH (KTOT/KC)         // 160
#define MTILES 17
#define NTILES (Hc/NTt)       // 8

// smem strides (in elements)
#define ASTR 68               // float2 per k-row of A (64 + 4 pad)
#define BSTR 136              // float  per k-row of B (128 + 8 pad)
#define ABUF (KC*ASTR)        // 2176 float2 per buffer
#define BBUF (KC*BSTR)        // 4352 float  per buffer

// ---------------- scratch (device globals) ---------------------------------
__device__ float g_A[(size_t)ROWS*KTOT];     // [Init|x0..x3] rows, tf32-rounded
__device__ float g_alpha[ROWS];
__device__ float g_wfT[(size_t)Hc*Hc];       // w_f transposed, K-major, tf32-rounded
__device__ int   g_perm[MTILES*MT];
__device__ int   g_meta[4];

// ---------------- helpers ---------------------------------------------------
__device__ __forceinline__ float to_tf32(float x){
    float r; asm("cvt.rna.tf32.f32 %0, %1;" : "=f"(r) : "f"(x)); return r;
}
__device__ __forceinline__ void mma8(float* c, const uint32_t* a, const uint32_t* b){
    asm volatile("mma.sync.aligned.m16n8k8.row.col.f32.tf32.tf32.f32 "
        "{%0,%1,%2,%3}, {%4,%5,%6,%7}, {%8,%9}, {%0,%1,%2,%3};"
        : "+f"(c[0]), "+f"(c[1]), "+f"(c[2]), "+f"(c[3])
        : "r"(a[0]), "r"(a[1]), "r"(a[2]), "r"(a[3]), "r"(b[0]), "r"(b[1]));
}

// ---------------- kernel 1: gather Init rows + alpha -----------------------
__global__ void k_gather(const float* __restrict__ we, const int* __restrict__ ids,
                         const float* __restrict__ w_alpha, const float* __restrict__ b_alpha) {
    int row = blockIdx.x;
    int b = row >> 7;
    int id = ids[row];
    int idc = min(max(id, 0), Sc - 1);
    const float* src = we + ((size_t)b*Sc + idc)*Hc;
    float partial = 0.f;
    #pragma unroll 4
    for (int h = threadIdx.x; h < Hc; h += 256) {
        float v = src[h];
        g_A[(size_t)row*KTOT + h] = to_tf32(v);
        partial += v * w_alpha[h];
    }
    __shared__ float red[256];
    red[threadIdx.x] = partial;
    __syncthreads();
    for (int s = 128; s > 0; s >>= 1) {
        if (threadIdx.x < s) red[threadIdx.x] += red[threadIdx.x + s];
        __syncthreads();
    }
    if (threadIdx.x == 0) {
        float x = red[0] + b_alpha[0];
        g_alpha[row] = 1.f / (1.f + expf(-x));
    }
}

// ---------------- kernel 1b: transpose w_f -> K-major (tf32) ---------------
__global__ void k_transpose(const float* __restrict__ w) {
    __shared__ float t[32][33];
    int bx = blockIdx.x*32, by = blockIdx.y*32;
    for (int r = threadIdx.y; r < 32; r += 8)
        t[r][threadIdx.x] = w[(size_t)(by + r)*Hc + bx + threadIdx.x];
    __syncthreads();
    for (int r = threadIdx.y; r < 32; r += 8)
        g_wfT[(size_t)(bx + r)*Hc + by + threadIdx.x] = to_tf32(t[threadIdx.x][r]);
}

// ---------------- kernel 2: sorted-prefix aggregation -> segs 1..4 ---------
// 128 threads (one h each), grid (Bc, Hc/128) = 128 CTAs for latency hiding.
__global__ void k_agg(const float* __restrict__ numbers, const int* __restrict__ is_resp,
                      const int* __restrict__ ids) {
    int b = blockIdx.x;
    int tid = threadIdx.x;
    int h = blockIdx.y * 128 + tid;
    __shared__ float s_num[Nc], s_w[Nc], s_scale[Nc];
    __shared__ int s_order[Nc], s_c[Nc];
    __shared__ unsigned char s_newgrp[Nc];
    __shared__ int s_cnt;
    if (tid == 0) s_cnt = 0;
    __syncthreads();
    {
        int i = tid;
        s_num[i] = numbers[b*Nc + i];
        s_c[i] = (is_resp[b*Nc + i] == 1) ? 1 : 0;
        int valid = (ids[b*Nc + i] >= 0) ? 1 : 0;
        s_w[i] = valid ? g_alpha[b*Nc + i] : 0.f;
        s_scale[i] = (float)valid;
        if (valid) atomicAdd(&s_cnt, 1);
    }
    __syncthreads();
    float denom = fmaxf((float)(s_cnt - 1), 1.f);
    {
        int i = tid;
        float ni = s_num[i];
        int pos = 0;
        for (int j = 0; j < Nc; j++) {
            float nj = s_num[j];
            pos += (int)((nj < ni) || (nj == ni && j < i));
        }
        s_order[pos] = i;
        s_scale[i] = s_scale[i] / denom;
    }
    __syncthreads();
    {
        int t = tid;
        s_newgrp[t] = (t == 0) || (s_num[s_order[t]] != s_num[s_order[t-1]]);
    }
    __syncthreads();

    const float* initb = g_A + (size_t)(b*Nc)*KTOT;
    float A0 = 0.f, A1 = 0.f;
    #pragma unroll 4
    for (int j = 0; j < Nc; j++) {
        float wv = s_w[j] * initb[(size_t)j*KTOT + h];
        if (s_c[j]) A1 += wv; else A0 += wv;
    }
    float p0 = 0.f, p1 = 0.f, r0 = 0.f, r1 = 0.f;
    for (int t = 0; t < Nc; t++) {
        int j = s_order[t];
        if (s_newgrp[t]) { p0 = r0; p1 = r1; }
        float v = initb[(size_t)j*KTOT + h];
        float wv = s_w[j] * v;
        float sc = s_scale[j];
        float sub0 = A0 - p0 - (s_c[j] == 0 ? wv : 0.f);
        float sub1 = A1 - p1 - (s_c[j] == 1 ? wv : 0.f);
        size_t xb = (size_t)(b*Nc + j)*KTOT + Hc + h;
        g_A[xb        ] = to_tf32(p0 * sc);
        g_A[xb +   Hc ] = to_tf32(p1 * sc);
        g_A[xb + 2*Hc ] = to_tf32(sub0 * sc);
        g_A[xb + 3*Hc ] = to_tf32(sub1 * sc);
        if (s_c[j]) r1 += wv; else r0 += wv;
    }
}

// ---------------- kernel 3: row permutation grouped by resp ----------------
__global__ void k_perm(const int* __restrict__ is_resp) {
    __shared__ int red[256];
    __shared__ int cnt[2];
    int tid = threadIdx.x;
    int local0 = 0;
    for (int r = tid; r < ROWS; r += 256)
        local0 += (is_resp[r] == 1) ? 0 : 1;
    red[tid] = local0;
    __syncthreads();
    for (int s = 128; s > 0; s >>= 1) {
        if (tid < s) red[tid] += red[tid + s];
        __syncthreads();
    }
    int n0 = red[0];
    int g0t = (n0 + MT - 1) / MT;
    if (tid == 0) { cnt[0] = 0; cnt[1] = g0t * MT; g_meta[0] = g0t; }
    for (int s = tid; s < MTILES*MT; s += 256) g_perm[s] = -1;
    __syncthreads();
    for (int r = tid; r < ROWS; r += 256) {
        int grp = (is_resp[r] == 1) ? 1 : 0;
        int pos = atomicAdd(&cnt[grp], 1);
        g_perm[pos] = r;
    }
}

// ---------------- kernel 4: tf32 mma.sync GEMM -----------------------------
// C[128x128] = A[128 x 5120 gathered] * B[5120 x 128]; bias + relu + scatter.
// 8 warps, warp tile 64x32. Fragment double-buffer over ks hides LDS latency.
__global__ void __launch_bounds__(256, 1)
k_mma(const float* __restrict__ b_f, const float* __restrict__ W_r,
      float* __restrict__ out) {
    extern __shared__ float sdyn[];
    float2* Abase = (float2*)sdyn;            // 2 x ABUF float2  (34816 B)
    float*  Bbase = sdyn + 2*ABUF*2;          // 2 x BBUF float   (34816 B)

    __shared__ int s_rows[MT];
    __shared__ const float* s_Bp[KSEGS];

    int tid = threadIdx.x;
    int wid = tid >> 5;
    int lane = tid & 31;
    int g = lane >> 2, tig = lane & 3;
    int wr = wid >> 2;                // 0..1  (64-row strip)
    int wc = wid & 3;                 // 0..3  (32-col strip)
    int mt = blockIdx.y, nt = blockIdx.x;
    int ncol = nt * NTt;

    if (tid < MT) s_rows[tid] = g_perm[mt*MT + tid];
    if (tid == 0) {
        int a = (mt >= g_meta[0]) ? 1 : 0;
        s_Bp[0] = g_wfT;
        s_Bp[1] = W_r + (size_t)(4 + 2*a)*Hc*Hc;   // raw fp32: HMMA truncates to tf32
        s_Bp[2] = W_r + (size_t)(5 + 2*a)*Hc*Hc;
        s_Bp[3] = W_r + (size_t)(2*a    )*Hc*Hc;
        s_Bp[4] = W_r + (size_t)(2*a + 1)*Hc*Hc;
    }
    __syncthreads();

    // ---- producer thread maps -------------------------------------------
    int mpA = tid & 63;
    int koA = tid >> 6;               // 0..3 -> k0 = 8*koA
    int mA0 = (mpA >> 3)*16 + (mpA & 7);
    int rA0 = s_rows[mA0], rA1 = s_rows[mA0 + 8];
    const float* pA0 = (rA0 >= 0) ? (g_A + (size_t)rA0*KTOT + 8*koA) : (const float*)0;
    const float* pA1 = (rA1 >= 0) ? (g_A + (size_t)rA1*KTOT + 8*koA) : (const float*)0;
    int nB[2], koB[2];
    #pragma unroll
    for (int t = 0; t < 2; t++) {
        int u = tid + t*256;
        nB[t] = u & 127;
        koB[t] = u >> 7;              // 0..3
    }

    float acc[4][4][4];
    #pragma unroll
    for (int i = 0; i < 4; i++)
        #pragma unroll
        for (int j = 0; j < 4; j++)
            #pragma unroll
            for (int q = 0; q < 4; q++) acc[i][j][q] = 0.f;

    float4 avA[4];
    float4 bvB[2][2];

    auto ldg_chunk = [&](int kc) {
        size_t kb = (size_t)kc*KC;
        if (pA0) { avA[0] = *(const float4*)(pA0 + kb); avA[1] = *(const float4*)(pA0 + kb + 4); }
        else     { avA[0] = make_float4(0,0,0,0); avA[1] = avA[0]; }
        if (pA1) { avA[2] = *(const float4*)(pA1 + kb); avA[3] = *(const float4*)(pA1 + kb + 4); }
        else     { avA[2] = make_float4(0,0,0,0); avA[3] = avA[2]; }
        const float* Bs = s_Bp[kc >> 5];
        int kin = (kc & 31) * KC;
        #pragma unroll
        for (int t = 0; t < 2; t++) {
            const float* p = Bs + (size_t)(ncol + nB[t])*Hc + kin + 8*koB[t];
            bvB[t][0] = *(const float4*)p;
            bvB[t][1] = *(const float4*)(p + 4);
        }
    };
    auto sts_chunk = [&](int b) {
        float2* Ap = Abase + b*ABUF;
        float*  Bp = Bbase + b*BBUF;
        #pragma unroll
        for (int q = 0; q < 4; q++) {
            float a00 = (&avA[0].x)[q], a01 = (&avA[1].x)[q];
            float a10 = (&avA[2].x)[q], a11 = (&avA[3].x)[q];
            Ap[(8*koA + q    )*ASTR + mpA] = make_float2(a00, a10);
            Ap[(8*koA + q + 4)*ASTR + mpA] = make_float2(a01, a11);
        }
        #pragma unroll
        for (int t = 0; t < 2; t++)
            #pragma unroll
            for (int q = 0; q < 4; q++) {
                Bp[(8*koB[t] + q    )*BSTR + nB[t]] = (&bvB[t][0].x)[q];
                Bp[(8*koB[t] + q + 4)*BSTR + nB[t]] = (&bvB[t][1].x)[q];
            }
    };

    ldg_chunk(0);
    sts_chunk(0);
    __syncthreads();

    uint32_t afr[2][4][4], bfr[2][4][2];

    for (int kc = 0; kc < NCH; kc++) {
        int cur = kc & 1;
        const float2* Ap = Abase + cur*ABUF;
        const float*  Bp = Bbase + cur*BBUF;

        // prefetch fragments for ks=0
        {
            int kr0 = tig, kr1 = tig + 4;
            #pragma unroll
            for (int rm = 0; rm < 4; rm++) {
                int mp = (4*wr + rm)*8 + g;
                float2 x = Ap[kr0*ASTR + mp];
                float2 y = Ap[kr1*ASTR + mp];
                afr[0][rm][0] = __float_as_uint(x.x);
                afr[0][rm][1] = __float_as_uint(x.y);
                afr[0][rm][2] = __float_as_uint(y.x);
                afr[0][rm][3] = __float_as_uint(y.y);
            }
            #pragma unroll
            for (int nb = 0; nb < 4; nb++) {
                int n = 32*wc + 8*nb + g;
                bfr[0][nb][0] = __float_as_uint(Bp[kr0*BSTR + n]);
                bfr[0][nb][1] = __float_as_uint(Bp[kr1*BSTR + n]);
            }
        }

        if (kc + 1 < NCH) ldg_chunk(kc + 1);

        #pragma unroll
        for (int ks = 0; ks < 4; ks++) {
            int fb = ks & 1;
            if (ks < 3) {                   // prefetch fragments for ks+1
                int kr0 = 8*(ks + 1) + tig, kr1 = kr0 + 4;
                #pragma unroll
                for (int rm = 0; rm < 4; rm++) {
                    int mp = (4*wr + rm)*8 + g;
                    float2 x = Ap[kr0*ASTR + mp];
                    float2 y = Ap[kr1*ASTR + mp];
                    afr[fb^1][rm][0] = __float_as_uint(x.x);
                    afr[fb^1][rm][1] = __float_as_uint(x.y);
                    afr[fb^1][rm][2] = __float_as_uint(y.x);
                    afr[fb^1][rm][3] = __float_as_uint(y.y);
                }
                #pragma unroll
                for (int nb = 0; nb < 4; nb++) {
                    int n = 32*wc + 8*nb + g;
                    bfr[fb^1][nb][0] = __float_as_uint(Bp[kr0*BSTR + n]);
                    bfr[fb^1][nb][1] = __float_as_uint(Bp[kr1*BSTR + n]);
                }
            }
            #pragma unroll
            for (int rm = 0; rm < 4; rm++)
                #pragma unroll
                for (int nb = 0; nb < 4; nb++)
                    mma8(acc[rm][nb], afr[fb][rm], bfr[fb][nb]);
        }

        if (kc + 1 < NCH) sts_chunk(cur ^ 1);
        __syncthreads();
    }

    // ---- epilogue: bias + relu + scatter --------------------------------
    #pragma unroll
    for (int rm = 0; rm < 4; rm++) {
        int m0 = 64*wr + 16*rm + g;
        int row0 = s_rows[m0], row1 = s_rows[m0 + 8];
        #pragma unroll
        for (int nb = 0; nb < 4; nb++) {
            int col = ncol + 32*wc + 8*nb + 2*tig;
            float b0v = b_f[col], b1v = b_f[col + 1];
            if (row0 >= 0) {
                float v0 = acc[rm][nb][0] + b0v; v0 = v0 > 0.f ? v0 : 0.f;
                float v1 = acc[rm][nb][1] + b1v; v1 = v1 > 0.f ? v1 : 0.f;
                *(float2*)(out + (size_t)row0*Hc + col) = make_float2(v0, v1);
            }
            if (row1 >= 0) {
                float v2 = acc[rm][nb][2] + b0v; v2 = v2 > 0.f ? v2 : 0.f;
                float v3 = acc[rm][nb][3] + b1v; v3 = v3 > 0.f ? v3 : 0.f;
                *(float2*)(out + (size_t)row1*Hc + col) = make_float2(v2, v3);
            }
        }
    }
}

// ---------------------------------------------------------------------------
extern "C" void kernel_launch(void* const* d_in, const int* in_sizes, int n_in,
                              void* d_out, int out_size) {
    const float* word_emb = (const float*)d_in[0];
    const int*   num_ids  = (const int*)  d_in[1];
    const int*   is_resp  = (const int*)  d_in[2];
    const float* numbers  = (const float*)d_in[3];
    const float* w_alpha  = (const float*)d_in[4];
    const float* b_alpha  = (const float*)d_in[5];
    const float* w_f      = (const float*)d_in[6];
    const float* b_f      = (const float*)d_in[7];
    const float* W_r      = (const float*)d_in[8];
    float* out = (float*)d_out;

    k_gather<<<ROWS, 256>>>(word_emb, num_ids, w_alpha, b_alpha);
    k_transpose<<<dim3(Hc/32, Hc/32), dim3(32, 8)>>>(w_f);
    k_agg<<<dim3(Bc, Hc/128), 128>>>(numbers, is_resp, num_ids);
    k_perm<<<1, 256>>>(is_resp);

    cudaFuncSetAttribute(k_mma, cudaFuncAttributeMaxDynamicSharedMemorySize, 69632);
    k_mma<<<dim3(NTILES, MTILES), 256, 69632>>>(b_f, W_r, out);
}

// round 14
// speedup vs baseline: 2.9504x; 1.5224x over previous
#include <cuda_runtime.h>
#include <math.h>
#include <stdint.h>

#define Bc 16
#define Sc 2048
#define Hc 1024
#define Nc 128
#define ROWS (Bc*Nc)          // 2048
#define KSEGS 5
#define KTOT (KSEGS*Hc)       // 5120
#define MT 128                // M tile
#define NTt 128               // N tile
#define KC 32                 // K chunk (fp32)
#define NCH (KTOT/KC)         // 160
#define MTILES 17
#define NTILES (Hc/NTt)       // 8

#define KCp 36                // padded smem row stride (floats): banks (4g+tig) distinct
#define TILE_F (128*KCp)      // 4608 floats per A or B tile
#define STAGE_F (2*TILE_F)    // 9216 floats = 36864 B per stage
#define NSTG 3
#define SMEM_BYTES (NSTG*STAGE_F*4)   // 110592

// ---------------- scratch (device globals) ---------------------------------
__device__ float g_A[(size_t)ROWS*KTOT];     // [Init|x0..x3] rows, tf32-rounded
__device__ float g_alpha[ROWS];
__device__ float g_wfT[(size_t)Hc*Hc];       // w_f transposed, K-major
__device__ int   g_perm[MTILES*MT];
__device__ int   g_meta[4];

// ---------------- helpers ---------------------------------------------------
__device__ __forceinline__ float to_tf32(float x){
    float r; asm("cvt.rna.tf32.f32 %0, %1;" : "=f"(r) : "f"(x)); return r;
}
__device__ __forceinline__ void mma8(float* c, const uint32_t* a, const uint32_t* b){
    asm volatile("mma.sync.aligned.m16n8k8.row.col.f32.tf32.tf32.f32 "
        "{%0,%1,%2,%3}, {%4,%5,%6,%7}, {%8,%9}, {%0,%1,%2,%3};"
        : "+f"(c[0]), "+f"(c[1]), "+f"(c[2]), "+f"(c[3])
        : "r"(a[0]), "r"(a[1]), "r"(a[2]), "r"(a[3]), "r"(b[0]), "r"(b[1]));
}
__device__ __forceinline__ void cpa16(uint32_t dst, const void* src, int sz){
    asm volatile("cp.async.ca.shared.global [%0], [%1], 16, %2;"
                 :: "r"(dst), "l"(src), "r"(sz) : "memory");
}

// ---------------- kernel 1: gather Init rows + alpha -----------------------
__global__ void k_gather(const float* __restrict__ we, const int* __restrict__ ids,
                         const float* __restrict__ w_alpha, const float* __restrict__ b_alpha) {
    int row = blockIdx.x;
    int b = row >> 7;
    int id = ids[row];
    int idc = min(max(id, 0), Sc - 1);
    const float* src = we + ((size_t)b*Sc + idc)*Hc;
    float partial = 0.f;
    #pragma unroll 4
    for (int h = threadIdx.x; h < Hc; h += 256) {
        float v = src[h];
        g_A[(size_t)row*KTOT + h] = to_tf32(v);
        partial += v * w_alpha[h];
    }
    __shared__ float red[256];
    red[threadIdx.x] = partial;
    __syncthreads();
    for (int s = 128; s > 0; s >>= 1) {
        if (threadIdx.x < s) red[threadIdx.x] += red[threadIdx.x + s];
        __syncthreads();
    }
    if (threadIdx.x == 0) {
        float x = red[0] + b_alpha[0];
        g_alpha[row] = 1.f / (1.f + expf(-x));
    }
}

// ---------------- kernel 1b: transpose w_f -> K-major (tf32) ---------------
__global__ void k_transpose(const float* __restrict__ w) {
    __shared__ float t[32][33];
    int bx = blockIdx.x*32, by = blockIdx.y*32;
    for (int r = threadIdx.y; r < 32; r += 8)
        t[r][threadIdx.x] = w[(size_t)(by + r)*Hc + bx + threadIdx.x];
    __syncthreads();
    for (int r = threadIdx.y; r < 32; r += 8)
        g_wfT[(size_t)(bx + r)*Hc + by + threadIdx.x] = to_tf32(t[threadIdx.x][r]);
}

// ---------------- kernel 2: sorted-prefix aggregation (float4) -------------
// grid (Bc, 2), block 128: each thread owns 4 consecutive h (one float4 lane).
__global__ void k_agg(const float* __restrict__ numbers, const int* __restrict__ is_resp,
                      const int* __restrict__ ids) {
    int b = blockIdx.x;
    int tid = threadIdx.x;
    int h4 = blockIdx.y * 128 + tid;            // float4 column 0..255
    __shared__ float s_num[Nc], s_w[Nc], s_scale[Nc];
    __shared__ int s_order[Nc], s_c[Nc];
    __shared__ unsigned char s_newgrp[Nc];
    __shared__ int s_cnt;
    if (tid == 0) s_cnt = 0;
    __syncthreads();
    {
        int i = tid;                             // 128 threads == Nc
        s_num[i] = numbers[b*Nc + i];
        s_c[i] = (is_resp[b*Nc + i] == 1) ? 1 : 0;
        int valid = (ids[b*Nc + i] >= 0) ? 1 : 0;
        s_w[i] = valid ? g_alpha[b*Nc + i] : 0.f;
        s_scale[i] = (float)valid;
        if (valid) atomicAdd(&s_cnt, 1);
    }
    __syncthreads();
    float denom = fmaxf((float)(s_cnt - 1), 1.f);
    {
        int i = tid;
        float ni = s_num[i];
        int pos = 0;
        for (int j = 0; j < Nc; j++) {
            float nj = s_num[j];
            pos += (int)((nj < ni) || (nj == ni && j < i));
        }
        s_order[pos] = i;
        s_scale[i] = s_scale[i] / denom;
    }
    __syncthreads();
    {
        int t = tid;
        s_newgrp[t] = (t == 0) || (s_num[s_order[t]] != s_num[s_order[t-1]]);
    }
    __syncthreads();

    const float4* initb = (const float4*)g_A + (size_t)(b*Nc)*(KTOT/4) + h4;
    float4 A0 = make_float4(0,0,0,0), A1 = A0;
    #pragma unroll 2
    for (int j = 0; j < Nc; j++) {
        float4 v = initb[(size_t)j*(KTOT/4)];
        float w = s_w[j];
        if (s_c[j]) { A1.x += w*v.x; A1.y += w*v.y; A1.z += w*v.z; A1.w += w*v.w; }
        else        { A0.x += w*v.x; A0.y += w*v.y; A0.z += w*v.z; A0.w += w*v.w; }
    }
    float4 p0 = make_float4(0,0,0,0), p1 = p0, r0 = p0, r1 = p0;
    float4 v = initb[(size_t)s_order[0]*(KTOT/4)];
    for (int t = 0; t < Nc; t++) {
        int j = s_order[t];
        float4 vn;
        if (t + 1 < Nc) vn = initb[(size_t)s_order[t+1]*(KTOT/4)];
        if (s_newgrp[t]) { p0 = r0; p1 = r1; }
        float w = s_w[j], sc = s_scale[j];
        int c = s_c[j];
        float4 wv = make_float4(w*v.x, w*v.y, w*v.z, w*v.w);
        float4 sub0, sub1;
        sub0.x = A0.x - p0.x - (c==0 ? wv.x : 0.f);
        sub0.y = A0.y - p0.y - (c==0 ? wv.y : 0.f);
        sub0.z = A0.z - p0.z - (c==0 ? wv.z : 0.f);
        sub0.w = A0.w - p0.w - (c==0 ? wv.w : 0.f);
        sub1.x = A1.x - p1.x - (c==1 ? wv.x : 0.f);
        sub1.y = A1.y - p1.y - (c==1 ? wv.y : 0.f);
        sub1.z = A1.z - p1.z - (c==1 ? wv.z : 0.f);
        sub1.w = A1.w - p1.w - (c==1 ? wv.w : 0.f);
        float4* xb = (float4*)g_A + (size_t)(b*Nc + j)*(KTOT/4) + (Hc/4) + h4;
        xb[0]        = make_float4(to_tf32(p0.x*sc), to_tf32(p0.y*sc), to_tf32(p0.z*sc), to_tf32(p0.w*sc));
        xb[Hc/4]     = make_float4(to_tf32(p1.x*sc), to_tf32(p1.y*sc), to_tf32(p1.z*sc), to_tf32(p1.w*sc));
        xb[2*(Hc/4)] = make_float4(to_tf32(sub0.x*sc), to_tf32(sub0.y*sc), to_tf32(sub0.z*sc), to_tf32(sub0.w*sc));
        xb[3*(Hc/4)] = make_float4(to_tf32(sub1.x*sc), to_tf32(sub1.y*sc), to_tf32(sub1.z*sc), to_tf32(sub1.w*sc));
        if (c) { r1.x += wv.x; r1.y += wv.y; r1.z += wv.z; r1.w += wv.w; }
        else   { r0.x += wv.x; r0.y += wv.y; r0.z += wv.z; r0.w += wv.w; }
        v = vn;
    }
}

// ---------------- kernel 3: row permutation (warp-aggregated atomics) ------
__global__ void k_perm(const int* __restrict__ is_resp) {
    __shared__ int red[256];
    __shared__ int cnt[2];
    int tid = threadIdx.x;
    int lane = tid & 31;
    unsigned lt = (1u << lane) - 1u;
    int local0 = 0;
    for (int r = tid; r < ROWS; r += 256)
        local0 += (is_resp[r] == 1) ? 0 : 1;
    red[tid] = local0;
    __syncthreads();
    for (int s = 128; s > 0; s >>= 1) {
        if (tid < s) red[tid] += red[tid + s];
        __syncthreads();
    }
    int n0 = red[0];
    int g0t = (n0 + MT - 1) / MT;
    if (tid == 0) { cnt[0] = 0; cnt[1] = g0t * MT; g_meta[0] = g0t; }
    for (int s = tid; s < MTILES*MT; s += 256) g_perm[s] = -1;
    __syncthreads();
    for (int r = tid; r < ROWS; r += 256) {
        int grp = (is_resp[r] == 1) ? 1 : 0;
        unsigned m1 = __ballot_sync(0xffffffffu, grp);
        unsigned m0 = ~m1;
        int l0 = __ffs(m0) - 1, l1 = __ffs(m1) - 1;
        int base0 = 0, base1 = 0;
        if (m0 && lane == l0) base0 = atomicAdd(&cnt[0], __popc(m0));
        if (m1 && lane == l1) base1 = atomicAdd(&cnt[1], __popc(m1));
        if (m0) base0 = __shfl_sync(0xffffffffu, base0, l0);
        if (m1) base1 = __shfl_sync(0xffffffffu, base1, l1);
        int pos = grp ? (base1 + __popc(m1 & lt)) : (base0 + __popc(m0 & lt));
        g_perm[pos] = r;
    }
}

// ---------------- kernel 4: tf32 mma.sync GEMM, cp.async 3-stage -----------
// 512 threads, 16 warps (4x4), warp tile 32x32. smem [row][36] padded layout.
__global__ void __launch_bounds__(512, 1)
k_mma(const float* __restrict__ b_f, const float* __restrict__ W_r,
      float* __restrict__ out) {
    extern __shared__ float sdyn[];
    __shared__ int s_rows[MT];
    __shared__ const float* s_Bp[KSEGS];

    int tid = threadIdx.x;
    int wid = tid >> 5;
    int lane = tid & 31;
    int g = lane >> 2, tig = lane & 3;
    int wr = wid >> 2;                // 0..3 (32-row strip)
    int wc = wid & 3;                 // 0..3 (32-col strip)
    int mt = blockIdx.y, nt = blockIdx.x;
    int ncol = nt * NTt;

    if (tid < MT) s_rows[tid] = g_perm[mt*MT + tid];
    if (tid == 0) {
        int a = (mt >= g_meta[0]) ? 1 : 0;
        s_Bp[0] = g_wfT;
        s_Bp[1] = W_r + (size_t)(4 + 2*a)*Hc*Hc;   // raw fp32: HMMA truncates
        s_Bp[2] = W_r + (size_t)(5 + 2*a)*Hc*Hc;
        s_Bp[3] = W_r + (size_t)(2*a    )*Hc*Hc;
        s_Bp[4] = W_r + (size_t)(2*a + 1)*Hc*Hc;
    }
    __syncthreads();

    // copy map: thread t owns 16B units t and t+512 of each 1024-unit tile.
    int mu0 = tid >> 3;               // row 0..63
    int seg = tid & 7;                // 16B segment within 128B row payload
    int mu1 = mu0 + 64;
    int rA0 = s_rows[mu0], rA1 = s_rows[mu1];
    const float* srcA0 = (rA0 >= 0) ? (g_A + (size_t)rA0*KTOT + seg*4) : g_A;
    const float* srcA1 = (rA1 >= 0) ? (g_A + (size_t)rA1*KTOT + seg*4) : g_A;
    int szA0 = (rA0 >= 0) ? 16 : 0;
    int szA1 = (rA1 >= 0) ? 16 : 0;
    int d0 = mu0*KCp*4 + seg*16;      // byte offset within a tile
    int d1 = mu1*KCp*4 + seg*16;
    size_t bc0 = (size_t)(ncol + mu0)*Hc + seg*4;
    size_t bc1 = (size_t)(ncol + mu1)*Hc + seg*4;
    uint32_t sb = (uint32_t)__cvta_generic_to_shared(sdyn);

    auto issue = [&](int kc) {
        int st = kc % NSTG;
        uint32_t ab = sb + st*(STAGE_F*4);
        uint32_t bb = ab + TILE_F*4;
        int koff = kc * KC;
        cpa16(ab + d0, srcA0 + koff, szA0);
        cpa16(ab + d1, srcA1 + koff, szA1);
        const float* Bs = s_Bp[kc >> 5];
        int kin = (kc & 31) * KC;
        cpa16(bb + d0, Bs + bc0 + kin, 16);
        cpa16(bb + d1, Bs + bc1 + kin, 16);
        asm volatile("cp.async.commit_group;" ::: "memory");
    };

    issue(0);
    issue(1);

    float acc[2][4][4];
    #pragma unroll
    for (int i = 0; i < 2; i++)
        #pragma unroll
        for (int j = 0; j < 4; j++)
            #pragma unroll
            for (int q = 0; q < 4; q++) acc[i][j][q] = 0.f;

    for (int kc = 0; kc < NCH; kc++) {
        if (kc + 1 < NCH) asm volatile("cp.async.wait_group 1;" ::: "memory");
        else              asm volatile("cp.async.wait_group 0;" ::: "memory");
        __syncthreads();
        if (kc + 2 < NCH) issue(kc + 2);

        const float* As = sdyn + (kc % NSTG)*STAGE_F;
        const float* Bs = As + TILE_F;
        #pragma unroll
        for (int ks = 0; ks < 4; ks++) {
            int k0 = 8*ks + tig;
            uint32_t afr[2][4], bfr[4][2];
            #pragma unroll
            for (int rm = 0; rm < 2; rm++) {
                int m = 32*wr + 16*rm + g;
                afr[rm][0] = __float_as_uint(As[m*KCp + k0]);
                afr[rm][1] = __float_as_uint(As[(m+8)*KCp + k0]);
                afr[rm][2] = __float_as_uint(As[m*KCp + k0 + 4]);
                afr[rm][3] = __float_as_uint(As[(m+8)*KCp + k0 + 4]);
            }
            #pragma unroll
            for (int nb = 0; nb < 4; nb++) {
                int n = 32*wc + 8*nb + g;
                bfr[nb][0] = __float_as_uint(Bs[n*KCp + k0]);
                bfr[nb][1] = __float_as_uint(Bs[n*KCp + k0 + 4]);
            }
            #pragma unroll
            for (int rm = 0; rm < 2; rm++)
                #pragma unroll
                for (int nb = 0; nb < 4; nb++)
                    mma8(acc[rm][nb], afr[rm], bfr[nb]);
        }
    }

    // ---- epilogue: bias + relu + scatter --------------------------------
    #pragma unroll
    for (int rm = 0; rm < 2; rm++) {
        int m0 = 32*wr + 16*rm + g;
        int row0 = s_rows[m0], row1 = s_rows[m0 + 8];
        #pragma unroll
        for (int nb = 0; nb < 4; nb++) {
            int col = ncol + 32*wc + 8*nb + 2*tig;
            float b0v = b_f[col], b1v = b_f[col + 1];
            if (row0 >= 0) {
                float v0 = acc[rm][nb][0] + b0v; v0 = v0 > 0.f ? v0 : 0.f;
                float v1 = acc[rm][nb][1] + b1v; v1 = v1 > 0.f ? v1 : 0.f;
                *(float2*)(out + (size_t)row0*Hc + col) = make_float2(v0, v1);
            }
            if (row1 >= 0) {
                float v2 = acc[rm][nb][2] + b0v; v2 = v2 > 0.f ? v2 : 0.f;
                float v3 = acc[rm][nb][3] + b1v; v3 = v3 > 0.f ? v3 : 0.f;
                *(float2*)(out + (size_t)row1*Hc + col) = make_float2(v2, v3);
            }
        }
    }
}

// ---------------------------------------------------------------------------
extern "C" void kernel_launch(void* const* d_in, const int* in_sizes, int n_in,
                              void* d_out, int out_size) {
    const float* word_emb = (const float*)d_in[0];
    const int*   num_ids  = (const int*)  d_in[1];
    const int*   is_resp  = (const int*)  d_in[2];
    const float* numbers  = (const float*)d_in[3];
    const float* w_alpha  = (const float*)d_in[4];
    const float* b_alpha  = (const float*)d_in[5];
    const float* w_f      = (const float*)d_in[6];
    const float* b_f      = (const float*)d_in[7];
    const float* W_r      = (const float*)d_in[8];
    float* out = (float*)d_out;

    k_gather<<<ROWS, 256>>>(word_emb, num_ids, w_alpha, b_alpha);
    k_transpose<<<dim3(Hc/32, Hc/32), dim3(32, 8)>>>(w_f);
    k_agg<<<dim3(Bc, 2), 128>>>(numbers, is_resp, num_ids);
    k_perm<<<1, 256>>>(is_resp);

    cudaFuncSetAttribute(k_mma, cudaFuncAttributeMaxDynamicSharedMemorySize, SMEM_BYTES);
    k_mma<<<dim3(NTILES, MTILES), 512, SMEM_BYTES>>>(b_f, W_r, out);
}